// round 15
// baseline (speedup 1.0000x reference)
#include <cuda_runtime.h>
#include <cuda_bf16.h>
#include <math.h>
#include <stdint.h>

#define DIMC   96
#define DINNER 192
#define DSTATE 16
#define DCONV  4
#define DTRANK 6
#define NSWAP  59
#define BSZ    2
#define SEQ    6400
#define TOK    (BSZ*SEQ)     // 12800
#define CHUNK  64
#define NCH    (SEQ/CHUNK)   // 100
#define XPO    38            // dt_r(6) | B(16) | C(16)
#define DBC_LD 64
#define CARRY_PER_Z (BSZ*NCH*DINNER*DSTATE)
#define NFLAGS (2*BSZ*NCH)   // 400

// ---------------- scratch (static device globals; no allocation) ------------
__device__ __align__(16) float g_xz [2*TOK*2*DINNER];   // x raw | z pre-silu'd
__device__ __align__(16) float g_dbc[2*TOK*DBC_LD];
__device__ __align__(16) float g_aggP[2*CARRY_PER_Z];
__device__ __align__(16) float g_aggF[2*CARRY_PER_Z];
__device__ __align__(16) float g_incH[2*CARRY_PER_Z];
__device__ int g_flags[NFLAGS];
// bf16 hi/lo split activations
__device__ __align__(16) __nv_bfloat16 g_xsh[2*TOK*DIMC];
__device__ __align__(16) __nv_bfloat16 g_xsl[2*TOK*DIMC];
__device__ __align__(16) __nv_bfloat16 g_xch[2*TOK*DINNER];
__device__ __align__(16) __nv_bfloat16 g_xcl[2*TOK*DINNER];
__device__ __align__(16) __nv_bfloat16 g_ygh[2*TOK*DINNER];
__device__ __align__(16) __nv_bfloat16 g_ygl[2*TOK*DINNER];
// bf16 hi/lo split weights
#define WIN_SZ  (2*DINNER*DIMC)
#define W2_SZ   (XPO*DINNER)
#define WO_SZ   (DIMC*DINNER)
__device__ __align__(16) __nv_bfloat16 g_wih[2*WIN_SZ];
__device__ __align__(16) __nv_bfloat16 g_wil[2*WIN_SZ];
__device__ __align__(16) __nv_bfloat16 g_w2h[2*W2_SZ];
__device__ __align__(16) __nv_bfloat16 g_w2l[2*W2_SZ];
__device__ __align__(16) __nv_bfloat16 g_woh[2*WO_SZ];
__device__ __align__(16) __nv_bfloat16 g_wol[2*WO_SZ];

// ================= helpers ===================================================
__device__ __forceinline__ uint32_t smem_u32(const void* p) {
    uint32_t a;
    asm("{ .reg .u64 t; cvta.to.shared.u64 t, %1; cvt.u32.u64 %0, t; }"
        : "=r"(a) : "l"(p));
    return a;
}
__device__ __forceinline__ uint2 pack4bf(float a, float b, float c, float d) {
    __nv_bfloat162 p0 = __floats2bfloat162_rn(a, b);
    __nv_bfloat162 p1 = __floats2bfloat162_rn(c, d);
    uint2 r;
    r.x = *reinterpret_cast<uint32_t*>(&p0);
    r.y = *reinterpret_cast<uint32_t*>(&p1);
    return r;
}
__device__ __forceinline__ void split_bf(float v, __nv_bfloat16& h, __nv_bfloat16& l) {
    h = __float2bfloat16(v);
    l = __float2bfloat16(v - __bfloat162float(h));
}
__device__ __forceinline__ void pow_tree(float p, float a[DSTATE]) {
    float p2 = p*p, p3 = p2*p, p4 = p2*p2;
    float p8 = p4*p4, p12 = p8*p4;
    a[0]=p;      a[1]=p2;      a[2]=p3;      a[3]=p4;
    a[4]=p4*p;   a[5]=p4*p2;   a[6]=p4*p3;   a[7]=p8;
    a[8]=p8*p;   a[9]=p8*p2;   a[10]=p8*p3;  a[11]=p12;
    a[12]=p12*p; a[13]=p12*p2; a[14]=p12*p3; a[15]=p8*p8;
}
__device__ __forceinline__ void softplus_pair(float v, float& dt, float& p) {
    if (v > 20.f) { dt = v; p = __expf(-v); }
    else {
        float e = __expf(v);
        float r = __fdividef(1.f, 1.f + e);
        dt = -__logf(r);
        p  = r;
    }
}
__device__ __forceinline__ float xrecon(const __nv_bfloat16* xh, const __nv_bfloat16* xl,
                                        size_t ofs) {
    return __bfloat162float(xh[ofs]) + __bfloat162float(xl[ofs]);
}
__device__ __forceinline__ bool alog_is_arange(const float* A_log, int d, float nA[DSTATE])
{
    bool fast = true;
    #pragma unroll
    for (int s = 0; s < DSTATE; s++) {
        nA[s] = -__expf(A_log[d*DSTATE + s]);
        fast = fast && (fabsf(nA[s] + (float)(s+1)) <= 1e-4f * (float)(s+1));
    }
    return fast;
}
#define LDMX4(r0, r1, r2, r3, addr) \
    asm volatile("ldmatrix.sync.aligned.m8n8.x4.shared.b16 {%0,%1,%2,%3}, [%4];" \
                 : "=r"(r0), "=r"(r1), "=r"(r2), "=r"(r3) : "r"(addr))
#define MMA16816(c, a, b0, b1) \
    asm volatile("mma.sync.aligned.m16n8k16.row.col.f32.bf16.bf16.f32 " \
                 "{%0,%1,%2,%3}, {%4,%5,%6,%7}, {%8,%9}, {%0,%1,%2,%3};" \
                 : "+f"((c)[0]), "+f"((c)[1]), "+f"((c)[2]), "+f"((c)[3]) \
                 : "r"((a)[0]), "r"((a)[1]), "r"((a)[2]), "r"((a)[3]), \
                   "r"(b0), "r"(b1))
#define CP_A16(dst, src) \
    asm volatile("cp.async.cg.shared.global [%0], [%1], 16;" \
                 :: "r"(dst), "l"(src))
#define CP_Z16(dst, src) \
    asm volatile("cp.async.cg.shared.global [%0], [%1], 16, 0;" \
                 :: "r"(dst), "l"(src))
#define CP_COMMIT asm volatile("cp.async.commit_group;" ::: "memory")

// ================= split-bf16 HMMA GEMM (double-buffered cp.async) ==========
// MODE 0: plain  MODE 2: +resid  MODE 3: silu for cols>=192 (z half)
#define KC    32
#define SLD3  40
#define ABUF3 (128*SLD3*2)
#define WBUF3 (64*SLD3*2)
#define STAGE_SZ (2*ABUF3 + 2*WBUF3)
#define SMEM_GEMM (2*STAGE_SZ)

template<int MODE, int K, int NTOT, int OS>
__global__ void __launch_bounds__(256, 3)
hmma_gemm_kernel(const __nv_bfloat16* __restrict__ Ah0, const __nv_bfloat16* __restrict__ Al0,
                 const __nv_bfloat16* __restrict__ Ah1, const __nv_bfloat16* __restrict__ Al1,
                 const __nv_bfloat16* __restrict__ Wh0, const __nv_bfloat16* __restrict__ Wl0,
                 const __nv_bfloat16* __restrict__ Wh1, const __nv_bfloat16* __restrict__ Wl1,
                 float* __restrict__ O0, float* __restrict__ O1,
                 const float* __restrict__ rs0, const float* __restrict__ rs1)
{
    extern __shared__ __align__(16) char sm[];
    int z = blockIdx.z;
    const __nv_bfloat16* Ah = z ? Ah1 : Ah0;
    const __nv_bfloat16* Al = z ? Al1 : Al0;
    const __nv_bfloat16* Wh = z ? Wh1 : Wh0;
    const __nv_bfloat16* Wl = z ? Wl1 : Wl0;
    float*       O     = z ? O1 : O0;
    const float* resid = z ? rs1 : rs0;

    int tid  = threadIdx.x;
    int wid  = tid >> 5;
    int lane = tid & 31;
    int wm   = wid & 3;
    int wn   = wid >> 2;
    int m0 = blockIdx.x * 128;
    int n0 = blockIdx.y * 64;

    uint32_t sbase = smem_u32(sm);
    uint32_t aoff = (uint32_t)(((wm*32 + (lane & 15))*SLD3 + ((lane >> 4) << 3)) * 2);
    uint32_t boff = (uint32_t)(((wn*32 + ((lane >> 4) << 3) + (lane & 7))*SLD3
                               + (((lane >> 3) & 1) << 3)) * 2);

    float acc[2][4][4] = {};
    constexpr int NCHK = K / KC;

    auto prefetch = [&](int s, int kb) {
        uint32_t st = sbase + (uint32_t)(s * STAGE_SZ);
        #pragma unroll
        for (int p = 0; p < 2; p++) {
            int i  = tid + p*256;
            int r  = i >> 2;
            int c8 = (i & 3) * 8;
            size_t go = (size_t)(m0 + r)*K + kb + c8;
            uint32_t so = st + (uint32_t)((r*SLD3 + c8) * 2);
            CP_A16(so, Ah + go);
            CP_A16(so + ABUF3, Al + go);
        }
        {
            int r  = tid >> 2;
            int c8 = (tid & 3) * 8;
            int n  = n0 + r;
            uint32_t so = st + (uint32_t)(2*ABUF3 + (r*SLD3 + c8) * 2);
            if (NTOT % 64 == 0 || n < NTOT) {
                size_t go = (size_t)n*K + kb + c8;
                CP_A16(so, Wh + go);
                CP_A16(so + WBUF3, Wl + go);
            } else {
                CP_Z16(so, Wh);
                CP_Z16(so + WBUF3, Wl);
            }
        }
        CP_COMMIT;
    };

    prefetch(0, 0);

    #pragma unroll
    for (int c = 0; c < NCHK; c++) {
        if (c + 1 < NCHK) {
            prefetch((c + 1) & 1, (c + 1) * KC);
            asm volatile("cp.async.wait_group 1;" ::: "memory");
        } else {
            asm volatile("cp.async.wait_group 0;" ::: "memory");
        }
        __syncthreads();

        uint32_t st = sbase + (uint32_t)((c & 1) * STAGE_SZ);
        #pragma unroll
        for (int ks = 0; ks < KC; ks += 16) {
            uint32_t ah[2][4], al[2][4], bh[2][4], bl[2][4];
            #pragma unroll
            for (int im = 0; im < 2; im++) {
                uint32_t ad = st + aoff + (uint32_t)(im*16*SLD3*2 + ks*2);
                LDMX4(ah[im][0], ah[im][1], ah[im][2], ah[im][3], ad);
                LDMX4(al[im][0], al[im][1], al[im][2], al[im][3], ad + ABUF3);
            }
            #pragma unroll
            for (int jn = 0; jn < 2; jn++) {
                uint32_t bd = st + (uint32_t)(2*ABUF3) + boff
                            + (uint32_t)(jn*16*SLD3*2 + ks*2);
                LDMX4(bh[jn][0], bh[jn][1], bh[jn][2], bh[jn][3], bd);
                LDMX4(bl[jn][0], bl[jn][1], bl[jn][2], bl[jn][3], bd + WBUF3);
            }
            #pragma unroll
            for (int im = 0; im < 2; im++) {
                #pragma unroll
                for (int j = 0; j < 4; j++) {
                    uint32_t b0h = bh[j >> 1][(j & 1)*2], b1h = bh[j >> 1][(j & 1)*2 + 1];
                    uint32_t b0l = bl[j >> 1][(j & 1)*2], b1l = bl[j >> 1][(j & 1)*2 + 1];
                    MMA16816(acc[im][j], ah[im], b0h, b1h);
                    MMA16816(acc[im][j], ah[im], b0l, b1l);
                    MMA16816(acc[im][j], al[im], b0h, b1h);
                }
            }
        }
        __syncthreads();
    }

    // ---- epilogue ----
    #pragma unroll
    for (int im = 0; im < 2; im++) {
        #pragma unroll
        for (int j = 0; j < 4; j++) {
            int col = n0 + wn*32 + j*8 + (lane & 3)*2;
            if (NTOT % 64 != 0 && col >= NTOT) continue;
            int r0 = m0 + wm*32 + im*16 + (lane >> 2);
            #pragma unroll
            for (int half = 0; half < 2; half++) {
                int row = r0 + half*8;
                float v0 = acc[im][j][half*2 + 0];
                float v1 = acc[im][j][half*2 + 1];
                if (MODE == 2) {
                    v0 += resid[(size_t)row*OS + col];
                    v1 += resid[(size_t)row*OS + col + 1];
                } else if (MODE == 3) {
                    if (col >= DINNER) {
                        v0 = v0 / (1.f + __expf(-v0));
                        v1 = v1 / (1.f + __expf(-v1));
                    }
                }
                *reinterpret_cast<float2*>(O + (size_t)row*OS + col) =
                    make_float2(v0, v1);
            }
        }
    }
}

// ---------------- K1: fused layernorm/swap/shuffle + weight prep + flag clear
#define PREP_PER_Z (WIN_SZ + W2_SZ + WO_SZ)
#define LN_BLOCKS  (TOK/8)
#define PREP_BLOCKS ((2*PREP_PER_Z + 255)/256)

__global__ void ln_prep_kernel(const float* __restrict__ x1,
                               const float* __restrict__ x2,
                               const float* __restrict__ g1, const float* __restrict__ b1,
                               const float* __restrict__ g2, const float* __restrict__ b2,
                               __nv_bfloat16* __restrict__ xsh,
                               __nv_bfloat16* __restrict__ xsl,
                               const float* __restrict__ iw0, const float* __restrict__ iw1,
                               const float* __restrict__ xp0, const float* __restrict__ xp1,
                               const float* __restrict__ ow0, const float* __restrict__ ow1,
                               __nv_bfloat16* __restrict__ wih, __nv_bfloat16* __restrict__ wil,
                               __nv_bfloat16* __restrict__ w2h, __nv_bfloat16* __restrict__ w2l,
                               __nv_bfloat16* __restrict__ woh, __nv_bfloat16* __restrict__ wol,
                               int* __restrict__ flags)
{
    if (blockIdx.x >= LN_BLOCKS) {
        int pb = blockIdx.x - LN_BLOCKS;
        // zero lookback flags (first two prep blocks)
        if (pb < 2) {
            int fidx = pb*256 + threadIdx.x;
            if (fidx < NFLAGS) flags[fidx] = 0;
        }
        int idx = pb*256 + threadIdx.x;
        if (idx >= 2*PREP_PER_Z) return;
        int z = idx / PREP_PER_Z;
        int e = idx % PREP_PER_Z;
        float v;
        __nv_bfloat16 *dh, *dl;
        if (e < WIN_SZ) {
            v  = (z ? iw1 : iw0)[e];
            dh = wih + (size_t)z*WIN_SZ + e;
            dl = wil + (size_t)z*WIN_SZ + e;
        } else if (e < WIN_SZ + W2_SZ) {
            int e2 = e - WIN_SZ;
            v  = (z ? xp1 : xp0)[e2];
            dh = w2h + (size_t)z*W2_SZ + e2;
            dl = w2l + (size_t)z*W2_SZ + e2;
        } else {
            int e3 = e - WIN_SZ - W2_SZ;
            v  = (z ? ow1 : ow0)[e3];
            dh = woh + (size_t)z*WO_SZ + e3;
            dl = wol + (size_t)z*WO_SZ + e3;
        }
        __nv_bfloat16 h, l;
        split_bf(v, h, l);
        *dh = h; *dl = l;
        return;
    }
    __shared__ float s1[8][DIMC];
    __shared__ float s2[8][DIMC];
    int w = threadIdx.x >> 5, lane = threadIdx.x & 31;
    int token = blockIdx.x * 8 + w;
    const float* p1 = x1 + (size_t)token*DIMC;
    const float* p2 = x2 + (size_t)token*DIMC;
    float a0 = p1[lane], a1 = p1[lane+32], a2 = p1[lane+64];
    float c0 = p2[lane], c1 = p2[lane+32], c2 = p2[lane+64];
    float sum1 = a0+a1+a2, sq1 = a0*a0+a1*a1+a2*a2;
    float sum2 = c0+c1+c2, sq2 = c0*c0+c1*c1+c2*c2;
    #pragma unroll
    for (int o = 16; o > 0; o >>= 1) {
        sum1 += __shfl_xor_sync(0xffffffffu, sum1, o);
        sq1  += __shfl_xor_sync(0xffffffffu, sq1,  o);
        sum2 += __shfl_xor_sync(0xffffffffu, sum2, o);
        sq2  += __shfl_xor_sync(0xffffffffu, sq2,  o);
    }
    float m1 = sum1 * (1.f/DIMC), v1 = sq1 * (1.f/DIMC) - m1*m1;
    float m2 = sum2 * (1.f/DIMC), v2 = sq2 * (1.f/DIMC) - m2*m2;
    float r1 = rsqrtf(v1 + 1e-5f), r2 = rsqrtf(v2 + 1e-5f);
    #pragma unroll
    for (int k = 0; k < 3; k++) {
        int ch = lane + 32*k;
        float xv = (k==0? a0 : k==1? a1 : a2);
        float yv = (k==0? c0 : k==1? c1 : c2);
        s1[w][ch] = (xv - m1) * r1 * g1[ch] + b1[ch];
        s2[w][ch] = (yv - m2) * r2 * g2[ch] + b2[ch];
    }
    __syncwarp();
    #pragma unroll
    for (int k = 0; k < 3; k++) {
        int ch  = lane + 32*k;
        int src = (ch & 1)*48 + (ch >> 1);
        float p2v = s2[w][src];
        float p1v = (src < NSWAP) ? s2[w][src] : s1[w][src];
        __nv_bfloat16 h, l;
        split_bf(p1v, h, l);
        xsh[(size_t)token*DIMC + ch] = h;
        xsl[(size_t)token*DIMC + ch] = l;
        split_bf(p2v, h, l);
        xsh[(size_t)(TOK + token)*DIMC + ch] = h;
        xsl[(size_t)(TOK + token)*DIMC + ch] = l;
    }
}

// ---------------- K3: depthwise causal conv(4)+silu -> bf16 hi/lo -----------
#define CTPB 4
__global__ void conv_silu_kernel(const float* __restrict__ xz,
                                 const float* __restrict__ cw0, const float* __restrict__ cw1,
                                 const float* __restrict__ cb0, const float* __restrict__ cb1,
                                 __nv_bfloat16* __restrict__ xch,
                                 __nv_bfloat16* __restrict__ xcl)
{
    int z = blockIdx.z;
    const float* cw = z ? cw1 : cw0;
    const float* cb = z ? cb1 : cb0;
    const float* xzp = xz + (size_t)z*TOK*2*DINNER;
    __nv_bfloat16* xchp = xch + (size_t)z*TOK*DINNER;
    __nv_bfloat16* xclp = xcl + (size_t)z*TOK*DINNER;

    int tid = threadIdx.x;
    int q   = tid % 48;
    int tb  = blockIdx.x * 4 + tid / 48;
    int b   = blockIdx.y;
    int t0  = tb * CTPB;
    int d   = q * 4;

    float w00=cw[(d+0)*4+0], w01=cw[(d+0)*4+1], w02=cw[(d+0)*4+2], w03=cw[(d+0)*4+3];
    float w10=cw[(d+1)*4+0], w11=cw[(d+1)*4+1], w12=cw[(d+1)*4+2], w13=cw[(d+1)*4+3];
    float w20=cw[(d+2)*4+0], w21=cw[(d+2)*4+1], w22=cw[(d+2)*4+2], w23=cw[(d+2)*4+3];
    float w30=cw[(d+3)*4+0], w31=cw[(d+3)*4+1], w32=cw[(d+3)*4+2], w33=cw[(d+3)*4+3];
    float4 bias = *reinterpret_cast<const float4*>(cb + d);

    const float* xrow = xzp + (size_t)(b*SEQ)*(2*DINNER) + d;
    float4 h0, h1, h2;
    {
        int tt = t0 - 3;
        h0 = (tt >= 0) ? *reinterpret_cast<const float4*>(xrow + (size_t)tt*(2*DINNER))
                       : make_float4(0.f,0.f,0.f,0.f);
        tt = t0 - 2;
        h1 = (tt >= 0) ? *reinterpret_cast<const float4*>(xrow + (size_t)tt*(2*DINNER))
                       : make_float4(0.f,0.f,0.f,0.f);
        tt = t0 - 1;
        h2 = (tt >= 0) ? *reinterpret_cast<const float4*>(xrow + (size_t)tt*(2*DINNER))
                       : make_float4(0.f,0.f,0.f,0.f);
    }
    #pragma unroll
    for (int t = t0; t < t0 + CTPB; t++) {
        float4 h3 = *reinterpret_cast<const float4*>(xrow + (size_t)t*(2*DINNER));
        float4 o;
        o.x = bias.x + w00*h0.x + w01*h1.x + w02*h2.x + w03*h3.x;
        o.y = bias.y + w10*h0.y + w11*h1.y + w12*h2.y + w13*h3.y;
        o.z = bias.z + w20*h0.z + w21*h1.z + w22*h2.z + w23*h3.z;
        o.w = bias.w + w30*h0.w + w31*h1.w + w32*h2.w + w33*h3.w;
        o.x = o.x / (1.f + __expf(-o.x));
        o.y = o.y / (1.f + __expf(-o.y));
        o.z = o.z / (1.f + __expf(-o.z));
        o.w = o.w / (1.f + __expf(-o.w));
        size_t ofs = (size_t)(b*SEQ + t)*DINNER + d;
        __nv_bfloat16 hs[4], ls[4];
        split_bf(o.x, hs[0], ls[0]); split_bf(o.y, hs[1], ls[1]);
        split_bf(o.z, hs[2], ls[2]); split_bf(o.w, hs[3], ls[3]);
        *reinterpret_cast<uint2*>(xchp + ofs) =
            pack4bf(__bfloat162float(hs[0]), __bfloat162float(hs[1]),
                    __bfloat162float(hs[2]), __bfloat162float(hs[3]));
        *reinterpret_cast<uint2*>(xclp + ofs) =
            pack4bf(__bfloat162float(ls[0]), __bfloat162float(ls[1]),
                    __bfloat162float(ls[2]), __bfloat162float(ls[3]));
        h0 = h1; h1 = h2; h2 = h3;
    }
}

// ---------------- K5: single-pass fused scan (decoupled lookback) -----------
__global__ void __launch_bounds__(DINNER, 3)
scan_fused_kernel(const float* __restrict__ dbc_,
                  const __nv_bfloat16* __restrict__ xch_,
                  const __nv_bfloat16* __restrict__ xcl_,
                  const float* __restrict__ xz_,
                  const float* __restrict__ Al0, const float* __restrict__ Al1,
                  const float* __restrict__ dw0, const float* __restrict__ dw1,
                  const float* __restrict__ db0, const float* __restrict__ db1,
                  const float* __restrict__ Dp0, const float* __restrict__ Dp1,
                  float* __restrict__ aggP_, float* __restrict__ aggF_,
                  float* __restrict__ incH_, int* __restrict__ flags,
                  __nv_bfloat16* __restrict__ ygh_,
                  __nv_bfloat16* __restrict__ ygl_)
{
    __shared__ float sT[CHUNK][40];
    int z = blockIdx.z;
    int b = blockIdx.y;
    int c = blockIdx.x;
    const float* A_log = z ? Al1 : Al0;
    const float* dtw_g = z ? dw1 : dw0;
    const float* dtb_g = z ? db1 : db0;
    const float* Dp    = z ? Dp1 : Dp0;
    const float* dbc = dbc_ + (size_t)z*TOK*DBC_LD;
    const __nv_bfloat16* xch = xch_ + (size_t)z*TOK*DINNER;
    const __nv_bfloat16* xcl = xcl_ + (size_t)z*TOK*DINNER;
    const float* xz  = xz_  + (size_t)z*TOK*2*DINNER;
    float* aggP = aggP_ + (size_t)z*CARRY_PER_Z;
    float* aggF = aggF_ + (size_t)z*CARRY_PER_Z;
    float* incH = incH_ + (size_t)z*CARRY_PER_Z;

    int d = threadIdx.x;
    int t0 = b*SEQ + c*CHUNK;
    for (int i = d; i < CHUNK*XPO; i += DINNER) {
        int tt = i / XPO, j = i % XPO;
        sT[tt][j] = dbc[(size_t)(t0+tt)*DBC_LD + j];
    }
    float nA[DSTATE], h[DSTATE];
    bool fast = alog_is_arange(A_log, d, nA);
    float dtw[DTRANK];
    #pragma unroll
    for (int j = 0; j < DTRANK; j++) dtw[j] = dtw_g[d*DTRANK + j];
    float dtb = dtb_g[d];
    float Dd = Dp[d];
    #pragma unroll
    for (int s = 0; s < DSTATE; s++) h[s] = 0.f;
    __syncthreads();

    // ---- pass 1: local aggregate ----
    float apl[DSTATE];
    if (fast) {
        float sdt = 0.f;
        for (int t = 0; t < CHUNK; t++) {
            const float* row = sT[t];
            float v = dtb;
            #pragma unroll
            for (int j = 0; j < DTRANK; j++) v = fmaf(row[j], dtw[j], v);
            float dt, p;
            softplus_pair(v, dt, p);
            float x   = xrecon(xch, xcl, (size_t)(t0+t)*DINNER + d);
            float dtx = dt * x;
            sdt += dt;
            float a[DSTATE];
            pow_tree(p, a);
            const float* bc = &row[6];
            #pragma unroll
            for (int s = 0; s < DSTATE; s++)
                h[s] = fmaf(a[s], h[s], dtx*bc[s]);
        }
        pow_tree(__expf(-sdt), apl);
    } else {
        #pragma unroll
        for (int s = 0; s < DSTATE; s++) apl[s] = 1.f;
        for (int t = 0; t < CHUNK; t++) {
            const float* row = sT[t];
            float v = dtb;
            #pragma unroll
            for (int j = 0; j < DTRANK; j++) v = fmaf(row[j], dtw[j], v);
            float dt, p;
            softplus_pair(v, dt, p);
            float x   = xrecon(xch, xcl, (size_t)(t0+t)*DINNER + d);
            float dtx = dt * x;
            const float* bc = &row[6];
            #pragma unroll
            for (int s = 0; s < DSTATE; s++) {
                float a = __expf(dt * nA[s]);
                h[s]  = a*h[s] + dtx*bc[s];
                apl[s] *= a;
            }
        }
    }

    size_t o  = ((size_t)(b*NCH + c)*DINNER + d)*DSTATE;
    int   fi  = (z*BSZ + b)*NCH + c;
    volatile int* vflags = (volatile int*)flags;

    float h_pref[DSTATE];
    if (c == 0) {
        #pragma unroll
        for (int s = 0; s < DSTATE; s++) {
            h_pref[s] = 0.f;
            incH[o+s] = h[s];
        }
        __threadfence();
        __syncthreads();
        if (d == 0) atomicExch(&flags[fi], 2);
    } else {
        #pragma unroll
        for (int s = 0; s < DSTATE; s++) {
            aggP[o+s] = apl[s];
            aggF[o+s] = h[s];
        }
        __threadfence();
        __syncthreads();
        if (d == 0) atomicExch(&flags[fi], 1);
        // lookback
        float Pa[DSTATE], Ha[DSTATE];
        #pragma unroll
        for (int s = 0; s < DSTATE; s++) { Pa[s] = 1.f; Ha[s] = 0.f; }
        int j = c - 1;
        while (true) {
            int f;
            do { f = vflags[(z*BSZ + b)*NCH + j]; } while (f == 0);
            __threadfence();
            size_t oj = ((size_t)(b*NCH + j)*DINNER + d)*DSTATE;
            if (f == 2) {
                #pragma unroll
                for (int s = 0; s < DSTATE; s++)
                    h_pref[s] = fmaf(Pa[s], incH[oj+s], Ha[s]);
                break;
            } else {
                #pragma unroll
                for (int s = 0; s < DSTATE; s++) {
                    Ha[s] = fmaf(Pa[s], aggF[oj+s], Ha[s]);
                    Pa[s] *= aggP[oj+s];
                }
                j--;
            }
        }
        // publish inclusive
        #pragma unroll
        for (int s = 0; s < DSTATE; s++)
            incH[o+s] = fmaf(apl[s], h_pref[s], h[s]);
        __threadfence();
        __syncthreads();
        if (d == 0) atomicExch(&flags[fi], 2);
    }

    // ---- pass 2: full recursion from true prefix -> yg ----
    __nv_bfloat16* ygh = ygh_ + (size_t)z*TOK*DINNER;
    __nv_bfloat16* ygl = ygl_ + (size_t)z*TOK*DINNER;
    #pragma unroll
    for (int s = 0; s < DSTATE; s++) h[s] = h_pref[s];

    if (fast) {
        #pragma unroll 2
        for (int tg = 0; tg < CHUNK; tg += 8) {
            float xv[8], zv[8];
            #pragma unroll
            for (int u = 0; u < 8; u++) {
                xv[u] = xrecon(xch, xcl, (size_t)(t0+tg+u)*DINNER + d);
                zv[u] = xz[(size_t)(t0+tg+u)*(2*DINNER) + DINNER + d];
            }
            #pragma unroll
            for (int u = 0; u < 8; u++) {
                const float* row = sT[tg+u];
                float v = dtb;
                #pragma unroll
                for (int j = 0; j < DTRANK; j++) v = fmaf(row[j], dtw[j], v);
                float dt, p;
                softplus_pair(v, dt, p);
                float x   = xv[u];
                float dtx = dt * x;
                float a[DSTATE];
                pow_tree(p, a);
                const float* bc = &row[6];
                float y0 = 0.f, y1 = 0.f, y2 = 0.f, y3 = 0.f;
                #pragma unroll
                for (int s = 0; s < DSTATE; s += 4) {
                    h[s]   = fmaf(a[s],   h[s],   dtx*bc[s]);
                    h[s+1] = fmaf(a[s+1], h[s+1], dtx*bc[s+1]);
                    h[s+2] = fmaf(a[s+2], h[s+2], dtx*bc[s+2]);
                    h[s+3] = fmaf(a[s+3], h[s+3], dtx*bc[s+3]);
                    y0 = fmaf(h[s],   bc[16+s],   y0);
                    y1 = fmaf(h[s+1], bc[16+s+1], y1);
                    y2 = fmaf(h[s+2], bc[16+s+2], y2);
                    y3 = fmaf(h[s+3], bc[16+s+3], y3);
                }
                float yv = (y0 + y1) + (y2 + y3) + x*Dd;
                float g  = yv * zv[u];
                __nv_bfloat16 hh, ll;
                split_bf(g, hh, ll);
                ygh[(size_t)(t0+tg+u)*DINNER + d] = hh;
                ygl[(size_t)(t0+tg+u)*DINNER + d] = ll;
            }
        }
    } else {
        for (int t = 0; t < CHUNK; t++) {
            const float* row = sT[t];
            float v = dtb;
            #pragma unroll
            for (int j = 0; j < DTRANK; j++) v = fmaf(row[j], dtw[j], v);
            float dt, p;
            softplus_pair(v, dt, p);
            float x   = xrecon(xch, xcl, (size_t)(t0+t)*DINNER + d);
            float dtx = dt * x;
            const float* bc = &row[6];
            float y = 0.f;
            #pragma unroll
            for (int s = 0; s < DSTATE; s++) {
                float a = __expf(dt * nA[s]);
                h[s] = a*h[s] + dtx*bc[s];
                y += h[s] * bc[16 + s];
            }
            float yv = y + x*Dd;
            float zz = xz[(size_t)(t0+t)*(2*DINNER) + DINNER + d];
            float g  = yv * zz;
            __nv_bfloat16 hh, ll;
            split_bf(g, hh, ll);
            ygh[(size_t)(t0+t)*DINNER + d] = hh;
            ygl[(size_t)(t0+t)*DINNER + d] = ll;
        }
    }
}

// ---------------- launch -----------------------------------------------------
extern "C" void kernel_launch(void* const* d_in, const int* in_sizes, int n_in,
                              void* d_out, int out_size)
{
    const float* x1   = (const float*)d_in[0];
    const float* x2   = (const float*)d_in[1];
    const float* ln1g = (const float*)d_in[2];
    const float* ln1b = (const float*)d_in[3];
    const float* ln2g = (const float*)d_in[4];
    const float* ln2b = (const float*)d_in[5];

    const float* in_w[2], *conv_w[2], *conv_b[2], *xproj_w[2], *dt_w[2],
               * dt_b[2], *A_log[2], *Dp[2], *out_w[2];
    for (int mi = 0; mi < 2; mi++) {
        int base = 6 + mi*9;
        in_w[mi]    = (const float*)d_in[base + 0];
        conv_w[mi]  = (const float*)d_in[base + 1];
        conv_b[mi]  = (const float*)d_in[base + 2];
        xproj_w[mi] = (const float*)d_in[base + 3];
        dt_w[mi]    = (const float*)d_in[base + 4];
        dt_b[mi]    = (const float*)d_in[base + 5];
        A_log[mi]   = (const float*)d_in[base + 6];
        Dp[mi]      = (const float*)d_in[base + 7];
        out_w[mi]   = (const float*)d_in[base + 8];
    }

    float *xz, *dbc, *aP, *aF, *iH;
    int* flg;
    __nv_bfloat16 *xsh, *xsl, *xch, *xcl, *ygh, *ygl, *wih, *wil, *w2h, *w2l, *woh, *wol;
    cudaGetSymbolAddress((void**)&xz,  g_xz);
    cudaGetSymbolAddress((void**)&dbc, g_dbc);
    cudaGetSymbolAddress((void**)&aP,  g_aggP);
    cudaGetSymbolAddress((void**)&aF,  g_aggF);
    cudaGetSymbolAddress((void**)&iH,  g_incH);
    cudaGetSymbolAddress((void**)&flg, g_flags);
    cudaGetSymbolAddress((void**)&xsh, g_xsh);
    cudaGetSymbolAddress((void**)&xsl, g_xsl);
    cudaGetSymbolAddress((void**)&xch, g_xch);
    cudaGetSymbolAddress((void**)&xcl, g_xcl);
    cudaGetSymbolAddress((void**)&ygh, g_ygh);
    cudaGetSymbolAddress((void**)&ygl, g_ygl);
    cudaGetSymbolAddress((void**)&wih, g_wih);
    cudaGetSymbolAddress((void**)&wil, g_wil);
    cudaGetSymbolAddress((void**)&w2h, g_w2h);
    cudaGetSymbolAddress((void**)&w2l, g_w2l);
    cudaGetSymbolAddress((void**)&woh, g_woh);
    cudaGetSymbolAddress((void**)&wol, g_wol);

    float* out0 = (float*)d_out;
    float* out1 = (float*)d_out + (size_t)TOK*DIMC;

    cudaFuncSetAttribute(hmma_gemm_kernel<3, 96, 384, 384>,
                         cudaFuncAttributeMaxDynamicSharedMemorySize, SMEM_GEMM);
    cudaFuncSetAttribute(hmma_gemm_kernel<0, 192, XPO, DBC_LD>,
                         cudaFuncAttributeMaxDynamicSharedMemorySize, SMEM_GEMM);
    cudaFuncSetAttribute(hmma_gemm_kernel<2, 192, 96, 96>,
                         cudaFuncAttributeMaxDynamicSharedMemorySize, SMEM_GEMM);

    ln_prep_kernel<<<LN_BLOCKS + PREP_BLOCKS, 256>>>(
        x1, x2, ln1g, ln1b, ln2g, ln2b, xsh, xsl,
        in_w[0], in_w[1], xproj_w[0], xproj_w[1],
        out_w[0], out_w[1], wih, wil, w2h, w2l, woh, wol, flg);

    {   // in_proj (z half pre-gated with silu)
        dim3 grid(TOK/128, 384/64, 2);
        hmma_gemm_kernel<3, 96, 384, 384><<<grid, 256, SMEM_GEMM>>>(
            xsh, xsl, xsh + (size_t)TOK*DIMC, xsl + (size_t)TOK*DIMC,
            wih, wil, wih + WIN_SZ, wil + WIN_SZ,
            xz, xz + (size_t)TOK*2*DINNER,
            nullptr, nullptr);
    }

    {   // depthwise conv + silu -> bf16 hi/lo
        dim3 grid(SEQ/CTPB/4, BSZ, 2);
        conv_silu_kernel<<<grid, 192>>>(xz, conv_w[0], conv_w[1],
                                        conv_b[0], conv_b[1], xch, xcl);
    }

    {   // xproj (raw 38 cols: dt_r | B | C) -> dbc
        dim3 grid(TOK/128, 1, 2);
        hmma_gemm_kernel<0, 192, XPO, DBC_LD><<<grid, 256, SMEM_GEMM>>>(
            xch, xcl, xch + (size_t)TOK*DINNER, xcl + (size_t)TOK*DINNER,
            w2h, w2l, w2h + W2_SZ, w2l + W2_SZ,
            dbc, dbc + (size_t)TOK*DBC_LD,
            nullptr, nullptr);
    }

    {   // single-pass fused scan
        dim3 grid(NCH, BSZ, 2);
        scan_fused_kernel<<<grid, DINNER>>>(
            dbc, xch, xcl, xz, A_log[0], A_log[1],
            dt_w[0], dt_w[1], dt_b[0], dt_b[1],
            Dp[0], Dp[1], aP, aF, iH, flg, ygh, ygl);
    }

    {   // out_proj + residual
        dim3 grid(TOK/128, (DIMC + 63)/64, 2);
        hmma_gemm_kernel<2, 192, 96, 96><<<grid, 256, SMEM_GEMM>>>(
            ygh, ygl, ygh + (size_t)TOK*DINNER, ygl + (size_t)TOK*DINNER,
            woh, wol, woh + WO_SZ, wol + WO_SZ,
            out0, out1,
            x1, x2);
    }
}

// round 16
// speedup vs baseline: 1.2197x; 1.2197x over previous
#include <cuda_runtime.h>
#include <cuda_bf16.h>
#include <math.h>
#include <stdint.h>

#define DIMC   96
#define DINNER 192
#define DSTATE 16
#define DCONV  4
#define DTRANK 6
#define NSWAP  59
#define BSZ    2
#define SEQ    6400
#define TOK    (BSZ*SEQ)     // 12800
#define CHUNK  64
#define NCH    (SEQ/CHUNK)   // 100
#define XPO    38            // dt_r(6) | B(16) | C(16)
#define DBC_LD 40            // packed row stride of dbc
#define CARRY_PER_Z (BSZ*NCH*DINNER*DSTATE)

// ---------------- scratch (static device globals; no allocation) ------------
__device__ __align__(16) float g_xz [2*TOK*2*DINNER];   // x raw | z pre-silu'd
__device__ __align__(16) float g_dbc[2*TOK*DBC_LD];
__device__ __align__(16) float g_carryP[2*CARRY_PER_Z];
__device__ __align__(16) float g_carryF[2*CARRY_PER_Z];
__device__ __align__(16) float g_hinit [2*CARRY_PER_Z];
// bf16 hi/lo split activations
__device__ __align__(16) __nv_bfloat16 g_xsh[2*TOK*DIMC];
__device__ __align__(16) __nv_bfloat16 g_xsl[2*TOK*DIMC];
__device__ __align__(16) __nv_bfloat16 g_xch[2*TOK*DINNER];
__device__ __align__(16) __nv_bfloat16 g_xcl[2*TOK*DINNER];
__device__ __align__(16) __nv_bfloat16 g_ygh[2*TOK*DINNER];
__device__ __align__(16) __nv_bfloat16 g_ygl[2*TOK*DINNER];
// bf16 hi/lo split weights
#define WIN_SZ  (2*DINNER*DIMC)        // 384*96
#define W2_SZ   (XPO*DINNER)           // 38*192
#define WO_SZ   (DIMC*DINNER)          // 96*192
__device__ __align__(16) __nv_bfloat16 g_wih[2*WIN_SZ];
__device__ __align__(16) __nv_bfloat16 g_wil[2*WIN_SZ];
__device__ __align__(16) __nv_bfloat16 g_w2h[2*W2_SZ];
__device__ __align__(16) __nv_bfloat16 g_w2l[2*W2_SZ];
__device__ __align__(16) __nv_bfloat16 g_woh[2*WO_SZ];
__device__ __align__(16) __nv_bfloat16 g_wol[2*WO_SZ];

// ================= helpers ===================================================
__device__ __forceinline__ uint32_t smem_u32(const void* p) {
    uint32_t a;
    asm("{ .reg .u64 t; cvta.to.shared.u64 t, %1; cvt.u32.u64 %0, t; }"
        : "=r"(a) : "l"(p));
    return a;
}
__device__ __forceinline__ uint2 pack4bf(float a, float b, float c, float d) {
    __nv_bfloat162 p0 = __floats2bfloat162_rn(a, b);
    __nv_bfloat162 p1 = __floats2bfloat162_rn(c, d);
    uint2 r;
    r.x = *reinterpret_cast<uint32_t*>(&p0);
    r.y = *reinterpret_cast<uint32_t*>(&p1);
    return r;
}
__device__ __forceinline__ void split_bf(float v, __nv_bfloat16& h, __nv_bfloat16& l) {
    h = __float2bfloat16(v);
    l = __float2bfloat16(v - __bfloat162float(h));
}
// log-depth powers a[s] = p^(s+1), s=0..15
__device__ __forceinline__ void pow_tree(float p, float a[DSTATE]) {
    float p2 = p*p, p3 = p2*p, p4 = p2*p2;
    float p8 = p4*p4, p12 = p8*p4;
    a[0]=p;      a[1]=p2;      a[2]=p3;      a[3]=p4;
    a[4]=p4*p;   a[5]=p4*p2;   a[6]=p4*p3;   a[7]=p8;
    a[8]=p8*p;   a[9]=p8*p2;   a[10]=p8*p3;  a[11]=p12;
    a[12]=p12*p; a[13]=p12*p2; a[14]=p12*p3; a[15]=p8*p8;
}
// dt = softplus(v), p = exp(-dt) sharing one exp; fast __logf variant
__device__ __forceinline__ void softplus_pair(float v, float& dt, float& p) {
    if (v > 20.f) { dt = v; p = __expf(-v); }
    else {
        float e = __expf(v);
        float r = __fdividef(1.f, 1.f + e);
        dt = -__logf(r);
        p  = r;
    }
}
__device__ __forceinline__ float xrecon(const __nv_bfloat16* xh, const __nv_bfloat16* xl,
                                        size_t ofs) {
    return __bfloat162float(xh[ofs]) + __bfloat162float(xl[ofs]);
}
__device__ __forceinline__ bool alog_is_arange(const float* A_log, int d, float nA[DSTATE])
{
    bool fast = true;
    #pragma unroll
    for (int s = 0; s < DSTATE; s++) {
        nA[s] = -__expf(A_log[d*DSTATE + s]);
        fast = fast && (fabsf(nA[s] + (float)(s+1)) <= 1e-4f * (float)(s+1));
    }
    return fast;
}
#define LDMX4(r0, r1, r2, r3, addr) \
    asm volatile("ldmatrix.sync.aligned.m8n8.x4.shared.b16 {%0,%1,%2,%3}, [%4];" \
                 : "=r"(r0), "=r"(r1), "=r"(r2), "=r"(r3) : "r"(addr))
#define MMA16816(c, a, b0, b1) \
    asm volatile("mma.sync.aligned.m16n8k16.row.col.f32.bf16.bf16.f32 " \
                 "{%0,%1,%2,%3}, {%4,%5,%6,%7}, {%8,%9}, {%0,%1,%2,%3};" \
                 : "+f"((c)[0]), "+f"((c)[1]), "+f"((c)[2]), "+f"((c)[3]) \
                 : "r"((a)[0]), "r"((a)[1]), "r"((a)[2]), "r"((a)[3]), \
                   "r"(b0), "r"(b1))
#define CP_A16(dst, src) \
    asm volatile("cp.async.cg.shared.global [%0], [%1], 16;" \
                 :: "r"(dst), "l"(src))
#define CP_Z16(dst, src) \
    asm volatile("cp.async.cg.shared.global [%0], [%1], 16, 0;" \
                 :: "r"(dst), "l"(src))
#define CP_COMMIT asm volatile("cp.async.commit_group;" ::: "memory")

// ================= split-bf16 HMMA GEMM (double-buffered cp.async) ==========
// MODE 0: plain  MODE 2: +resid  MODE 3: silu for cols>=192 (z half)
#define KC    32
#define SLD3  40
#define ABUF3 (128*SLD3*2)
#define WBUF3 (64*SLD3*2)
#define STAGE_SZ (2*ABUF3 + 2*WBUF3)     // 30720 B
#define SMEM_GEMM (2*STAGE_SZ)           // 61440 B

template<int MODE, int K, int NTOT, int OS>
__global__ void __launch_bounds__(256, 3)
hmma_gemm_kernel(const __nv_bfloat16* __restrict__ Ah0, const __nv_bfloat16* __restrict__ Al0,
                 const __nv_bfloat16* __restrict__ Ah1, const __nv_bfloat16* __restrict__ Al1,
                 const __nv_bfloat16* __restrict__ Wh0, const __nv_bfloat16* __restrict__ Wl0,
                 const __nv_bfloat16* __restrict__ Wh1, const __nv_bfloat16* __restrict__ Wl1,
                 float* __restrict__ O0, float* __restrict__ O1,
                 const float* __restrict__ rs0, const float* __restrict__ rs1)
{
    extern __shared__ __align__(16) char sm[];
    int z = blockIdx.z;
    const __nv_bfloat16* Ah = z ? Ah1 : Ah0;
    const __nv_bfloat16* Al = z ? Al1 : Al0;
    const __nv_bfloat16* Wh = z ? Wh1 : Wh0;
    const __nv_bfloat16* Wl = z ? Wl1 : Wl0;
    float*       O     = z ? O1 : O0;
    const float* resid = z ? rs1 : rs0;

    int tid  = threadIdx.x;
    int wid  = tid >> 5;
    int lane = tid & 31;
    int wm   = wid & 3;
    int wn   = wid >> 2;
    int m0 = blockIdx.x * 128;
    int n0 = blockIdx.y * 64;

    uint32_t sbase = smem_u32(sm);
    uint32_t aoff = (uint32_t)(((wm*32 + (lane & 15))*SLD3 + ((lane >> 4) << 3)) * 2);
    uint32_t boff = (uint32_t)(((wn*32 + ((lane >> 4) << 3) + (lane & 7))*SLD3
                               + (((lane >> 3) & 1) << 3)) * 2);

    float acc[2][4][4] = {};
    constexpr int NCHK = K / KC;

    auto prefetch = [&](int s, int kb) {
        uint32_t st = sbase + (uint32_t)(s * STAGE_SZ);
        #pragma unroll
        for (int p = 0; p < 2; p++) {
            int i  = tid + p*256;
            int r  = i >> 2;
            int c8 = (i & 3) * 8;
            size_t go = (size_t)(m0 + r)*K + kb + c8;
            uint32_t so = st + (uint32_t)((r*SLD3 + c8) * 2);
            CP_A16(so, Ah + go);
            CP_A16(so + ABUF3, Al + go);
        }
        {
            int r  = tid >> 2;
            int c8 = (tid & 3) * 8;
            int n  = n0 + r;
            uint32_t so = st + (uint32_t)(2*ABUF3 + (r*SLD3 + c8) * 2);
            if (NTOT % 64 == 0 || n < NTOT) {
                size_t go = (size_t)n*K + kb + c8;
                CP_A16(so, Wh + go);
                CP_A16(so + WBUF3, Wl + go);
            } else {
                CP_Z16(so, Wh);
                CP_Z16(so + WBUF3, Wl);
            }
        }
        CP_COMMIT;
    };

    prefetch(0, 0);

    #pragma unroll
    for (int c = 0; c < NCHK; c++) {
        if (c + 1 < NCHK) {
            prefetch((c + 1) & 1, (c + 1) * KC);
            asm volatile("cp.async.wait_group 1;" ::: "memory");
        } else {
            asm volatile("cp.async.wait_group 0;" ::: "memory");
        }
        __syncthreads();

        uint32_t st = sbase + (uint32_t)((c & 1) * STAGE_SZ);
        #pragma unroll
        for (int ks = 0; ks < KC; ks += 16) {
            uint32_t ah[2][4], al[2][4], bh[2][4], bl[2][4];
            #pragma unroll
            for (int im = 0; im < 2; im++) {
                uint32_t ad = st + aoff + (uint32_t)(im*16*SLD3*2 + ks*2);
                LDMX4(ah[im][0], ah[im][1], ah[im][2], ah[im][3], ad);
                LDMX4(al[im][0], al[im][1], al[im][2], al[im][3], ad + ABUF3);
            }
            #pragma unroll
            for (int jn = 0; jn < 2; jn++) {
                uint32_t bd = st + (uint32_t)(2*ABUF3) + boff
                            + (uint32_t)(jn*16*SLD3*2 + ks*2);
                LDMX4(bh[jn][0], bh[jn][1], bh[jn][2], bh[jn][3], bd);
                LDMX4(bl[jn][0], bl[jn][1], bl[jn][2], bl[jn][3], bd + WBUF3);
            }
            #pragma unroll
            for (int im = 0; im < 2; im++) {
                #pragma unroll
                for (int j = 0; j < 4; j++) {
                    uint32_t b0h = bh[j >> 1][(j & 1)*2], b1h = bh[j >> 1][(j & 1)*2 + 1];
                    uint32_t b0l = bl[j >> 1][(j & 1)*2], b1l = bl[j >> 1][(j & 1)*2 + 1];
                    MMA16816(acc[im][j], ah[im], b0h, b1h);
                    MMA16816(acc[im][j], ah[im], b0l, b1l);
                    MMA16816(acc[im][j], al[im], b0h, b1h);
                }
            }
        }
        __syncthreads();
    }

    // ---- epilogue ----
    #pragma unroll
    for (int im = 0; im < 2; im++) {
        #pragma unroll
        for (int j = 0; j < 4; j++) {
            int col = n0 + wn*32 + j*8 + (lane & 3)*2;
            if (NTOT % 64 != 0 && col >= NTOT) continue;
            int r0 = m0 + wm*32 + im*16 + (lane >> 2);
            #pragma unroll
            for (int half = 0; half < 2; half++) {
                int row = r0 + half*8;
                float v0 = acc[im][j][half*2 + 0];
                float v1 = acc[im][j][half*2 + 1];
                if (MODE == 2) {
                    v0 += resid[(size_t)row*OS + col];
                    v1 += resid[(size_t)row*OS + col + 1];
                } else if (MODE == 3) {
                    if (col >= DINNER) {
                        v0 = v0 / (1.f + __expf(-v0));
                        v1 = v1 / (1.f + __expf(-v1));
                    }
                }
                *reinterpret_cast<float2*>(O + (size_t)row*OS + col) =
                    make_float2(v0, v1);
            }
        }
    }
}

// ---------------- K1: fused layernorm/swap/shuffle + weight prep ------------
#define PREP_PER_Z (WIN_SZ + W2_SZ + WO_SZ)
#define LN_BLOCKS  (TOK/8)
#define PREP_BLOCKS ((2*PREP_PER_Z + 255)/256)

__global__ void ln_prep_kernel(const float* __restrict__ x1,
                               const float* __restrict__ x2,
                               const float* __restrict__ g1, const float* __restrict__ b1,
                               const float* __restrict__ g2, const float* __restrict__ b2,
                               __nv_bfloat16* __restrict__ xsh,
                               __nv_bfloat16* __restrict__ xsl,
                               const float* __restrict__ iw0, const float* __restrict__ iw1,
                               const float* __restrict__ xp0, const float* __restrict__ xp1,
                               const float* __restrict__ ow0, const float* __restrict__ ow1,
                               __nv_bfloat16* __restrict__ wih, __nv_bfloat16* __restrict__ wil,
                               __nv_bfloat16* __restrict__ w2h, __nv_bfloat16* __restrict__ w2l,
                               __nv_bfloat16* __restrict__ woh, __nv_bfloat16* __restrict__ wol)
{
    if (blockIdx.x >= LN_BLOCKS) {
        int idx = (blockIdx.x - LN_BLOCKS)*256 + threadIdx.x;
        if (idx >= 2*PREP_PER_Z) return;
        int z = idx / PREP_PER_Z;
        int e = idx % PREP_PER_Z;
        float v;
        __nv_bfloat16 *dh, *dl;
        if (e < WIN_SZ) {
            v  = (z ? iw1 : iw0)[e];
            dh = wih + (size_t)z*WIN_SZ + e;
            dl = wil + (size_t)z*WIN_SZ + e;
        } else if (e < WIN_SZ + W2_SZ) {
            int e2 = e - WIN_SZ;
            v  = (z ? xp1 : xp0)[e2];
            dh = w2h + (size_t)z*W2_SZ + e2;
            dl = w2l + (size_t)z*W2_SZ + e2;
        } else {
            int e3 = e - WIN_SZ - W2_SZ;
            v  = (z ? ow1 : ow0)[e3];
            dh = woh + (size_t)z*WO_SZ + e3;
            dl = wol + (size_t)z*WO_SZ + e3;
        }
        __nv_bfloat16 h, l;
        split_bf(v, h, l);
        *dh = h; *dl = l;
        return;
    }
    __shared__ float s1[8][DIMC];
    __shared__ float s2[8][DIMC];
    int w = threadIdx.x >> 5, lane = threadIdx.x & 31;
    int token = blockIdx.x * 8 + w;
    const float* p1 = x1 + (size_t)token*DIMC;
    const float* p2 = x2 + (size_t)token*DIMC;
    float a0 = p1[lane], a1 = p1[lane+32], a2 = p1[lane+64];
    float c0 = p2[lane], c1 = p2[lane+32], c2 = p2[lane+64];
    float sum1 = a0+a1+a2, sq1 = a0*a0+a1*a1+a2*a2;
    float sum2 = c0+c1+c2, sq2 = c0*c0+c1*c1+c2*c2;
    #pragma unroll
    for (int o = 16; o > 0; o >>= 1) {
        sum1 += __shfl_xor_sync(0xffffffffu, sum1, o);
        sq1  += __shfl_xor_sync(0xffffffffu, sq1,  o);
        sum2 += __shfl_xor_sync(0xffffffffu, sum2, o);
        sq2  += __shfl_xor_sync(0xffffffffu, sq2,  o);
    }
    float m1 = sum1 * (1.f/DIMC), v1 = sq1 * (1.f/DIMC) - m1*m1;
    float m2 = sum2 * (1.f/DIMC), v2 = sq2 * (1.f/DIMC) - m2*m2;
    float r1 = rsqrtf(v1 + 1e-5f), r2 = rsqrtf(v2 + 1e-5f);
    #pragma unroll
    for (int k = 0; k < 3; k++) {
        int ch = lane + 32*k;
        float xv = (k==0? a0 : k==1? a1 : a2);
        float yv = (k==0? c0 : k==1? c1 : c2);
        s1[w][ch] = (xv - m1) * r1 * g1[ch] + b1[ch];
        s2[w][ch] = (yv - m2) * r2 * g2[ch] + b2[ch];
    }
    __syncwarp();
    #pragma unroll
    for (int k = 0; k < 3; k++) {
        int ch  = lane + 32*k;
        int src = (ch & 1)*48 + (ch >> 1);
        float p2v = s2[w][src];
        float p1v = (src < NSWAP) ? s2[w][src] : s1[w][src];
        __nv_bfloat16 h, l;
        split_bf(p1v, h, l);
        xsh[(size_t)token*DIMC + ch] = h;
        xsl[(size_t)token*DIMC + ch] = l;
        split_bf(p2v, h, l);
        xsh[(size_t)(TOK + token)*DIMC + ch] = h;
        xsl[(size_t)(TOK + token)*DIMC + ch] = l;
    }
}

// ---------------- K3: depthwise causal conv(4)+silu -> bf16 hi/lo -----------
#define CTPB 4
__global__ void conv_silu_kernel(const float* __restrict__ xz,
                                 const float* __restrict__ cw0, const float* __restrict__ cw1,
                                 const float* __restrict__ cb0, const float* __restrict__ cb1,
                                 __nv_bfloat16* __restrict__ xch,
                                 __nv_bfloat16* __restrict__ xcl)
{
    int z = blockIdx.z;
    const float* cw = z ? cw1 : cw0;
    const float* cb = z ? cb1 : cb0;
    const float* xzp = xz + (size_t)z*TOK*2*DINNER;
    __nv_bfloat16* xchp = xch + (size_t)z*TOK*DINNER;
    __nv_bfloat16* xclp = xcl + (size_t)z*TOK*DINNER;

    int tid = threadIdx.x;
    int q   = tid % 48;
    int tb  = blockIdx.x * 4 + tid / 48;
    int b   = blockIdx.y;
    int t0  = tb * CTPB;
    int d   = q * 4;

    float w00=cw[(d+0)*4+0], w01=cw[(d+0)*4+1], w02=cw[(d+0)*4+2], w03=cw[(d+0)*4+3];
    float w10=cw[(d+1)*4+0], w11=cw[(d+1)*4+1], w12=cw[(d+1)*4+2], w13=cw[(d+1)*4+3];
    float w20=cw[(d+2)*4+0], w21=cw[(d+2)*4+1], w22=cw[(d+2)*4+2], w23=cw[(d+2)*4+3];
    float w30=cw[(d+3)*4+0], w31=cw[(d+3)*4+1], w32=cw[(d+3)*4+2], w33=cw[(d+3)*4+3];
    float4 bias = *reinterpret_cast<const float4*>(cb + d);

    const float* xrow = xzp + (size_t)(b*SEQ)*(2*DINNER) + d;
    float4 h0, h1, h2;
    {
        int tt = t0 - 3;
        h0 = (tt >= 0) ? *reinterpret_cast<const float4*>(xrow + (size_t)tt*(2*DINNER))
                       : make_float4(0.f,0.f,0.f,0.f);
        tt = t0 - 2;
        h1 = (tt >= 0) ? *reinterpret_cast<const float4*>(xrow + (size_t)tt*(2*DINNER))
                       : make_float4(0.f,0.f,0.f,0.f);
        tt = t0 - 1;
        h2 = (tt >= 0) ? *reinterpret_cast<const float4*>(xrow + (size_t)tt*(2*DINNER))
                       : make_float4(0.f,0.f,0.f,0.f);
    }
    #pragma unroll
    for (int t = t0; t < t0 + CTPB; t++) {
        float4 h3 = *reinterpret_cast<const float4*>(xrow + (size_t)t*(2*DINNER));
        float4 o;
        o.x = bias.x + w00*h0.x + w01*h1.x + w02*h2.x + w03*h3.x;
        o.y = bias.y + w10*h0.y + w11*h1.y + w12*h2.y + w13*h3.y;
        o.z = bias.z + w20*h0.z + w21*h1.z + w22*h2.z + w23*h3.z;
        o.w = bias.w + w30*h0.w + w31*h1.w + w32*h2.w + w33*h3.w;
        o.x = o.x / (1.f + __expf(-o.x));
        o.y = o.y / (1.f + __expf(-o.y));
        o.z = o.z / (1.f + __expf(-o.z));
        o.w = o.w / (1.f + __expf(-o.w));
        size_t ofs = (size_t)(b*SEQ + t)*DINNER + d;
        __nv_bfloat16 hs[4], ls[4];
        split_bf(o.x, hs[0], ls[0]); split_bf(o.y, hs[1], ls[1]);
        split_bf(o.z, hs[2], ls[2]); split_bf(o.w, hs[3], ls[3]);
        *reinterpret_cast<uint2*>(xchp + ofs) =
            pack4bf(__bfloat162float(hs[0]), __bfloat162float(hs[1]),
                    __bfloat162float(hs[2]), __bfloat162float(hs[3]));
        *reinterpret_cast<uint2*>(xclp + ofs) =
            pack4bf(__bfloat162float(ls[0]), __bfloat162float(ls[1]),
                    __bfloat162float(ls[2]), __bfloat162float(ls[3]));
        h0 = h1; h1 = h2; h2 = h3;
    }
}

// ---------------- K5: scan phase A (per-chunk carry, zero init) -------------
__global__ void scan_phaseA_kernel(const float* __restrict__ dbc_,
                                   const __nv_bfloat16* __restrict__ xch_,
                                   const __nv_bfloat16* __restrict__ xcl_,
                                   const float* __restrict__ Al0, const float* __restrict__ Al1,
                                   const float* __restrict__ dw0, const float* __restrict__ dw1,
                                   const float* __restrict__ db0, const float* __restrict__ db1,
                                   float* __restrict__ carryP_,
                                   float* __restrict__ carryF_)
{
    __shared__ float sT[CHUNK][40];
    int z = blockIdx.z;
    const float* A_log = z ? Al1 : Al0;
    const float* dtw_g = z ? dw1 : dw0;
    const float* dtb_g = z ? db1 : db0;
    const float* dbc = dbc_ + (size_t)z*TOK*DBC_LD;
    const __nv_bfloat16* xch = xch_ + (size_t)z*TOK*DINNER;
    const __nv_bfloat16* xcl = xcl_ + (size_t)z*TOK*DINNER;
    float* carryP = carryP_ + (size_t)z*CARRY_PER_Z;
    float* carryF = carryF_ + (size_t)z*CARRY_PER_Z;

    int d = threadIdx.x;
    int c = blockIdx.x;
    int b = blockIdx.y;
    int t0 = b*SEQ + c*CHUNK;
    for (int i = d; i < CHUNK*XPO; i += DINNER) {
        int tt = i / XPO, j = i % XPO;
        sT[tt][j] = dbc[(size_t)(t0+tt)*DBC_LD + j];
    }
    float nA[DSTATE], h[DSTATE];
    bool fast = alog_is_arange(A_log, d, nA);
    float dtw[DTRANK];
    #pragma unroll
    for (int j = 0; j < DTRANK; j++) dtw[j] = dtw_g[d*DTRANK + j];
    float dtb = dtb_g[d];
    #pragma unroll
    for (int s = 0; s < DSTATE; s++) h[s] = 0.f;
    __syncthreads();

    size_t o = ((size_t)(b*NCH + c)*DINNER + d)*DSTATE;
    if (fast) {
        float sdt = 0.f;
        #pragma unroll 2
        for (int tg = 0; tg < CHUNK; tg += 8) {
            float xv[8];
            #pragma unroll
            for (int u = 0; u < 8; u++)
                xv[u] = xrecon(xch, xcl, (size_t)(t0+tg+u)*DINNER + d);
            #pragma unroll
            for (int u = 0; u < 8; u++) {
                const float* row = sT[tg+u];
                float v = dtb;
                #pragma unroll
                for (int j = 0; j < DTRANK; j++) v = fmaf(row[j], dtw[j], v);
                float dt, p;
                softplus_pair(v, dt, p);
                float dtx = dt * xv[u];
                sdt += dt;
                float a[DSTATE];
                pow_tree(p, a);
                const float* bc = &row[6];
                #pragma unroll
                for (int s = 0; s < DSTATE; s++)
                    h[s] = fmaf(a[s], h[s], dtx*bc[s]);
            }
        }
        float qv = __expf(-sdt);
        float ap[DSTATE];
        pow_tree(qv, ap);
        #pragma unroll
        for (int s = 0; s < DSTATE; s++) {
            carryP[o+s] = ap[s]; carryF[o+s] = h[s];
        }
    } else {
        float ap[DSTATE];
        #pragma unroll
        for (int s = 0; s < DSTATE; s++) ap[s] = 1.f;
        for (int t = 0; t < CHUNK; t++) {
            const float* row = sT[t];
            float v = dtb;
            #pragma unroll
            for (int j = 0; j < DTRANK; j++) v = fmaf(row[j], dtw[j], v);
            float dt, p;
            softplus_pair(v, dt, p);
            float x   = xrecon(xch, xcl, (size_t)(t0+t)*DINNER + d);
            float dtx = dt * x;
            const float* bc = &row[6];
            #pragma unroll
            for (int s = 0; s < DSTATE; s++) {
                float a = __expf(dt * nA[s]);
                h[s]  = a*h[s] + dtx*bc[s];
                ap[s] *= a;
            }
        }
        #pragma unroll
        for (int s = 0; s < DSTATE; s++) { carryP[o+s] = ap[s]; carryF[o+s] = h[s]; }
    }
}

// ---------------- K6: scan phase B (sequential carry combine) ---------------
__global__ void scan_phaseB_kernel(const float* __restrict__ carryP,
                                   const float* __restrict__ carryF,
                                   float* __restrict__ hinit)
{
    int idx = blockIdx.x * blockDim.x + threadIdx.x;
    if (idx >= 2*BSZ*DINNER*DSTATE) return;
    int z  = idx / (BSZ*DINNER*DSTATE);
    int r  = idx % (BSZ*DINNER*DSTATE);
    int b  = r / (DINNER*DSTATE);
    int ds = r % (DINNER*DSTATE);
    size_t zoff = (size_t)z*CARRY_PER_Z;
    float h = 0.f;
    #pragma unroll 4
    for (int c = 0; c < NCH; c++) {
        size_t o = zoff + (size_t)(b*NCH + c)*(DINNER*DSTATE) + ds;
        hinit[o] = h;
        h = carryF[o] + carryP[o]*h;
    }
}

// ---------------- K7: scan phase C -> yg bf16 hi/lo -------------------------
__global__ void scan_phaseC_kernel(const float* __restrict__ dbc_,
                                   const __nv_bfloat16* __restrict__ xch_,
                                   const __nv_bfloat16* __restrict__ xcl_,
                                   const float* __restrict__ xz_,
                                   const float* __restrict__ Al0, const float* __restrict__ Al1,
                                   const float* __restrict__ dw0, const float* __restrict__ dw1,
                                   const float* __restrict__ db0, const float* __restrict__ db1,
                                   const float* __restrict__ Dp0, const float* __restrict__ Dp1,
                                   const float* __restrict__ hinit_,
                                   __nv_bfloat16* __restrict__ ygh_,
                                   __nv_bfloat16* __restrict__ ygl_)
{
    __shared__ float sT[CHUNK][40];
    int z = blockIdx.z;
    const float* A_log = z ? Al1 : Al0;
    const float* dtw_g = z ? dw1 : dw0;
    const float* dtb_g = z ? db1 : db0;
    const float* Dp    = z ? Dp1 : Dp0;
    const float* dbc = dbc_ + (size_t)z*TOK*DBC_LD;
    const __nv_bfloat16* xch = xch_ + (size_t)z*TOK*DINNER;
    const __nv_bfloat16* xcl = xcl_ + (size_t)z*TOK*DINNER;
    const float* xz  = xz_  + (size_t)z*TOK*2*DINNER;
    const float* hinit = hinit_ + (size_t)z*CARRY_PER_Z;
    __nv_bfloat16* ygh = ygh_ + (size_t)z*TOK*DINNER;
    __nv_bfloat16* ygl = ygl_ + (size_t)z*TOK*DINNER;

    int d = threadIdx.x;
    int c = blockIdx.x;
    int b = blockIdx.y;
    int t0 = b*SEQ + c*CHUNK;
    for (int i = d; i < CHUNK*XPO; i += DINNER) {
        int tt = i / XPO, j = i % XPO;
        sT[tt][j] = dbc[(size_t)(t0+tt)*DBC_LD + j];
    }
    float nA[DSTATE], h[DSTATE];
    bool fast = alog_is_arange(A_log, d, nA);
    float dtw[DTRANK];
    #pragma unroll
    for (int j = 0; j < DTRANK; j++) dtw[j] = dtw_g[d*DTRANK + j];
    float dtb = dtb_g[d];
    size_t hb = (size_t)(b*NCH + c)*(DINNER*DSTATE) + d*DSTATE;
    #pragma unroll
    for (int s = 0; s < DSTATE; s++) h[s] = hinit[hb + s];
    float Dd = Dp[d];
    __syncthreads();

    if (fast) {
        #pragma unroll 2
        for (int tg = 0; tg < CHUNK; tg += 8) {
            float xv[8], zv[8];
            #pragma unroll
            for (int u = 0; u < 8; u++) {
                xv[u] = xrecon(xch, xcl, (size_t)(t0+tg+u)*DINNER + d);
                zv[u] = xz[(size_t)(t0+tg+u)*(2*DINNER) + DINNER + d];  // pre-silu'd
            }
            #pragma unroll
            for (int u = 0; u < 8; u++) {
                const float* row = sT[tg+u];
                float v = dtb;
                #pragma unroll
                for (int j = 0; j < DTRANK; j++) v = fmaf(row[j], dtw[j], v);
                float dt, p;
                softplus_pair(v, dt, p);
                float x   = xv[u];
                float dtx = dt * x;
                float a[DSTATE];
                pow_tree(p, a);
                const float* bc = &row[6];
                float y0 = 0.f, y1 = 0.f, y2 = 0.f, y3 = 0.f;
                #pragma unroll
                for (int s = 0; s < DSTATE; s += 4) {
                    h[s]   = fmaf(a[s],   h[s],   dtx*bc[s]);
                    h[s+1] = fmaf(a[s+1], h[s+1], dtx*bc[s+1]);
                    h[s+2] = fmaf(a[s+2], h[s+2], dtx*bc[s+2]);
                    h[s+3] = fmaf(a[s+3], h[s+3], dtx*bc[s+3]);
                    y0 = fmaf(h[s],   bc[16+s],   y0);
                    y1 = fmaf(h[s+1], bc[16+s+1], y1);
                    y2 = fmaf(h[s+2], bc[16+s+2], y2);
                    y3 = fmaf(h[s+3], bc[16+s+3], y3);
                }
                float yv = (y0 + y1) + (y2 + y3) + x*Dd;
                float g  = yv * zv[u];
                __nv_bfloat16 hh, ll;
                split_bf(g, hh, ll);
                ygh[(size_t)(t0+tg+u)*DINNER + d] = hh;
                ygl[(size_t)(t0+tg+u)*DINNER + d] = ll;
            }
        }
    } else {
        for (int t = 0; t < CHUNK; t++) {
            const float* row = sT[t];
            float v = dtb;
            #pragma unroll
            for (int j = 0; j < DTRANK; j++) v = fmaf(row[j], dtw[j], v);
            float dt, p;
            softplus_pair(v, dt, p);
            float x   = xrecon(xch, xcl, (size_t)(t0+t)*DINNER + d);
            float dtx = dt * x;
            const float* bc = &row[6];
            float y = 0.f;
            #pragma unroll
            for (int s = 0; s < DSTATE; s++) {
                float a = __expf(dt * nA[s]);
                h[s] = a*h[s] + dtx*bc[s];
                y += h[s] * bc[16 + s];
            }
            float yv = y + x*Dd;
            float zz = xz[(size_t)(t0+t)*(2*DINNER) + DINNER + d];  // pre-silu'd
            float g  = yv * zz;
            __nv_bfloat16 hh, ll;
            split_bf(g, hh, ll);
            ygh[(size_t)(t0+t)*DINNER + d] = hh;
            ygl[(size_t)(t0+t)*DINNER + d] = ll;
        }
    }
}

// ---------------- launch -----------------------------------------------------
extern "C" void kernel_launch(void* const* d_in, const int* in_sizes, int n_in,
                              void* d_out, int out_size)
{
    const float* x1   = (const float*)d_in[0];
    const float* x2   = (const float*)d_in[1];
    const float* ln1g = (const float*)d_in[2];
    const float* ln1b = (const float*)d_in[3];
    const float* ln2g = (const float*)d_in[4];
    const float* ln2b = (const float*)d_in[5];

    const float* in_w[2], *conv_w[2], *conv_b[2], *xproj_w[2], *dt_w[2],
               * dt_b[2], *A_log[2], *Dp[2], *out_w[2];
    for (int mi = 0; mi < 2; mi++) {
        int base = 6 + mi*9;
        in_w[mi]    = (const float*)d_in[base + 0];
        conv_w[mi]  = (const float*)d_in[base + 1];
        conv_b[mi]  = (const float*)d_in[base + 2];
        xproj_w[mi] = (const float*)d_in[base + 3];
        dt_w[mi]    = (const float*)d_in[base + 4];
        dt_b[mi]    = (const float*)d_in[base + 5];
        A_log[mi]   = (const float*)d_in[base + 6];
        Dp[mi]      = (const float*)d_in[base + 7];
        out_w[mi]   = (const float*)d_in[base + 8];
    }

    float *xz, *dbc, *cP, *cF, *hin;
    __nv_bfloat16 *xsh, *xsl, *xch, *xcl, *ygh, *ygl, *wih, *wil, *w2h, *w2l, *woh, *wol;
    cudaGetSymbolAddress((void**)&xz,  g_xz);
    cudaGetSymbolAddress((void**)&dbc, g_dbc);
    cudaGetSymbolAddress((void**)&cP,  g_carryP);
    cudaGetSymbolAddress((void**)&cF,  g_carryF);
    cudaGetSymbolAddress((void**)&hin, g_hinit);
    cudaGetSymbolAddress((void**)&xsh, g_xsh);
    cudaGetSymbolAddress((void**)&xsl, g_xsl);
    cudaGetSymbolAddress((void**)&xch, g_xch);
    cudaGetSymbolAddress((void**)&xcl, g_xcl);
    cudaGetSymbolAddress((void**)&ygh, g_ygh);
    cudaGetSymbolAddress((void**)&ygl, g_ygl);
    cudaGetSymbolAddress((void**)&wih, g_wih);
    cudaGetSymbolAddress((void**)&wil, g_wil);
    cudaGetSymbolAddress((void**)&w2h, g_w2h);
    cudaGetSymbolAddress((void**)&w2l, g_w2l);
    cudaGetSymbolAddress((void**)&woh, g_woh);
    cudaGetSymbolAddress((void**)&wol, g_wol);

    float* out0 = (float*)d_out;
    float* out1 = (float*)d_out + (size_t)TOK*DIMC;

    cudaFuncSetAttribute(hmma_gemm_kernel<3, 96, 384, 384>,
                         cudaFuncAttributeMaxDynamicSharedMemorySize, SMEM_GEMM);
    cudaFuncSetAttribute(hmma_gemm_kernel<0, 192, XPO, DBC_LD>,
                         cudaFuncAttributeMaxDynamicSharedMemorySize, SMEM_GEMM);
    cudaFuncSetAttribute(hmma_gemm_kernel<2, 192, 96, 96>,
                         cudaFuncAttributeMaxDynamicSharedMemorySize, SMEM_GEMM);

    ln_prep_kernel<<<LN_BLOCKS + PREP_BLOCKS, 256>>>(
        x1, x2, ln1g, ln1b, ln2g, ln2b, xsh, xsl,
        in_w[0], in_w[1], xproj_w[0], xproj_w[1],
        out_w[0], out_w[1], wih, wil, w2h, w2l, woh, wol);

    {   // in_proj (z half pre-gated with silu)
        dim3 grid(TOK/128, 384/64, 2);
        hmma_gemm_kernel<3, 96, 384, 384><<<grid, 256, SMEM_GEMM>>>(
            xsh, xsl, xsh + (size_t)TOK*DIMC, xsl + (size_t)TOK*DIMC,
            wih, wil, wih + WIN_SZ, wil + WIN_SZ,
            xz, xz + (size_t)TOK*2*DINNER,
            nullptr, nullptr);
    }

    {   // depthwise conv + silu -> bf16 hi/lo only
        dim3 grid(SEQ/CTPB/4, BSZ, 2);
        conv_silu_kernel<<<grid, 192>>>(xz, conv_w[0], conv_w[1],
                                        conv_b[0], conv_b[1], xch, xcl);
    }

    {   // xproj (raw 38 cols: dt_r | B | C) -> dbc (packed LD=40)
        dim3 grid(TOK/128, 1, 2);
        hmma_gemm_kernel<0, 192, XPO, DBC_LD><<<grid, 256, SMEM_GEMM>>>(
            xch, xcl, xch + (size_t)TOK*DINNER, xcl + (size_t)TOK*DINNER,
            w2h, w2l, w2h + W2_SZ, w2l + W2_SZ,
            dbc, dbc + (size_t)TOK*DBC_LD,
            nullptr, nullptr);
    }

    {   // chunked parallel scan
        dim3 grid(NCH, BSZ, 2);
        scan_phaseA_kernel<<<grid, DINNER>>>(dbc, xch, xcl, A_log[0], A_log[1],
                                             dt_w[0], dt_w[1], dt_b[0], dt_b[1],
                                             cP, cF);
        scan_phaseB_kernel<<<(2*BSZ*DINNER*DSTATE + 255)/256, 256>>>(cP, cF, hin);
        scan_phaseC_kernel<<<grid, DINNER>>>(dbc, xch, xcl, xz, A_log[0], A_log[1],
                                             dt_w[0], dt_w[1], dt_b[0], dt_b[1],
                                             Dp[0], Dp[1], hin, ygh, ygl);
    }

    {   // out_proj + residual
        dim3 grid(TOK/128, (DIMC + 63)/64, 2);
        hmma_gemm_kernel<2, 192, 96, 96><<<grid, 256, SMEM_GEMM>>>(
            ygh, ygl, ygh + (size_t)TOK*DINNER, ygl + (size_t)TOK*DINNER,
            woh, wol, woh + WO_SZ, wol + WO_SZ,
            out0, out1,
            x1, x2);
    }
}